// round 11
// baseline (speedup 1.0000x reference)
#include <cuda_runtime.h>
#include <cuda_fp16.h>
#include <cstdint>

// out[b,o] = sum_i tanh(x[b,i]*t) * W[o,i],  W = sum_p coef[o,i,p]
// B=131072, I=O=128. fp32 in/out.
//
// mma.sync.m16n8k16 fp16 (fp32 accum), fp16 W (rel_err ~2.7e-4).
// R9 base + M-split mainloop (16 live accs -> ~48 regs, 5 CTAs/SM, no spills).

static constexpr int IDIM = 128;
static constexpr int ODIM = 128;
static constexpr int TILE_M = 64;

// B fragments, paired layout: block (kt, nt2) of 32 lanes x uint4 =
// [ntg=2*nt2 reg0, reg1, ntg=2*nt2+1 reg0, reg1]. 32KB, L1/L2-hot.
__device__ uint32_t g_BF[8 * 8 * 32 * 4];

// ---------------------------------------------------------------------------
__global__ void prep_w_kernel(const float* __restrict__ coef) {
    int idx = blockIdx.x * blockDim.x + threadIdx.x;   // 0..8191
    int nt = idx >> 9;
    int kt = (idx >> 6) & 7;
    int lane = (idx >> 1) & 31;
    int reg = idx & 1;
    int n = nt * 8 + (lane >> 2);
    int k = kt * 16 + (lane & 3) * 2 + reg * 8;

    const float4* c0 = reinterpret_cast<const float4*>(coef + ((size_t)n * 128 + k) * 16);
    const float4* c1 = reinterpret_cast<const float4*>(coef + ((size_t)n * 128 + k + 1) * 16);
    float4 v[8];
#pragma unroll
    for (int j = 0; j < 4; j++) v[j] = c0[j];
#pragma unroll
    for (int j = 0; j < 4; j++) v[4 + j] = c1[j];
    float s0 = 0.f, s1 = 0.f;
#pragma unroll
    for (int j = 0; j < 4; j++) s0 += (v[j].x + v[j].y) + (v[j].z + v[j].w);
#pragma unroll
    for (int j = 0; j < 4; j++) s1 += (v[4 + j].x + v[4 + j].y) + (v[4 + j].z + v[4 + j].w);
    __half2 hh = __floats2half2_rn(s0, s1);
    int pos = ((kt * 8 + (nt >> 1)) * 32 + lane) * 4 + (nt & 1) * 2 + reg;
    g_BF[pos] = *reinterpret_cast<uint32_t*>(&hh);
}

// ---------------------------------------------------------------------------
// 5-op tanh: tanh(v*t) = 1 - 2/(e^{2vt}+1), e via ex2.approx. Clamp-free.
// ---------------------------------------------------------------------------
__device__ __forceinline__ float tanh_fast(float v, float c) {
    float e, r;
    asm("ex2.approx.f32 %0, %1;" : "=f"(e) : "f"(v * c));
    asm("rcp.approx.f32 %0, %1;" : "=f"(r) : "f"(e + 1.f));
    return fmaf(-2.f, r, 1.f);
}

__device__ __forceinline__ uint32_t pack_h2(float a, float b) {
    __half2 h = __floats2half2_rn(a, b);
    return *reinterpret_cast<uint32_t*>(&h);
}

#define MMA16816(d0, d1, d2, d3, a0, a1, a2, a3, b0, b1)                      \
    asm volatile(                                                             \
        "mma.sync.aligned.m16n8k16.row.col.f32.f16.f16.f32 "                  \
        "{%0,%1,%2,%3}, {%4,%5,%6,%7}, {%8,%9}, {%0,%1,%2,%3};"               \
        : "+f"(d0), "+f"(d1), "+f"(d2), "+f"(d3)                              \
        : "r"(a0), "r"(a1), "r"(a2), "r"(a3), "r"(b0), "r"(b1))

#define LDMATRIX_X4(a0, a1, a2, a3, addr)                                     \
    asm volatile(                                                             \
        "ldmatrix.sync.aligned.m8n8.x4.shared.b16 {%0,%1,%2,%3}, [%4];"       \
        : "=r"(a0), "=r"(a1), "=r"(a2), "=r"(a3) : "r"(addr))

// SMEM: 32KB = A tile 16KB (64 rows x 256B, XOR-16B swizzle)
//             + staging 16KB (32 rows x 512B fp32, XOR-32B swizzle).
static constexpr int SMEM_STG = 16384;
static constexpr int SMEM_TOTAL = 32768;

// ---------------------------------------------------------------------------
__global__ __launch_bounds__(256, 5) void fused_tanh_gemm_kernel(
    const float* __restrict__ x, const float* __restrict__ tanh_range,
    float* __restrict__ out)
{
    extern __shared__ __align__(16) char smem[];
    uint32_t sbase;
    asm("{ .reg .u64 t; cvta.to.shared.u64 t, %1; cvt.u32.u64 %0, t; }"
        : "=r"(sbase) : "l"(smem));

    const int tid = threadIdx.x;
    const int lane = tid & 31;
    const int wid = tid >> 5;
    const int mgroup = wid >> 2;
    const int ngroup = wid & 3;
    const size_t rowBase = (size_t)blockIdx.x * TILE_M;

    // ---- stage 1: front-batched coalesced loads + 5-op tanh + swizzled STS ----
    // (independent of prep_w output; overlaps with prep_w under PDL)
    {
        const float c = __ldg(tanh_range) * 2.885390082f;   // 2*log2(e)*t
        const float4* x4 = reinterpret_cast<const float4*>(x + rowBase * IDIM);
#pragma unroll
        for (int g = 0; g < 2; g++) {
            float4 v[4];
#pragma unroll
            for (int p = 0; p < 4; p++)
                v[p] = __ldcs(&x4[(wid * 8 + g * 4 + p) * 32 + lane]);
#pragma unroll
            for (int p = 0; p < 4; p++) {
                int row = wid * 8 + g * 4 + p;
                uint2 hp;
                hp.x = pack_h2(tanh_fast(v[p].x, c), tanh_fast(v[p].y, c));
                hp.y = pack_h2(tanh_fast(v[p].z, c), tanh_fast(v[p].w, c));
                uint32_t byte = (uint32_t)row * 256 + ((lane * 8) ^ ((row & 7) << 4));
                *reinterpret_cast<uint2*>(smem + byte) = hp;
            }
        }
    }

    // prep_w must be complete before any g_BF read
    cudaGridDependencySynchronize();
    __syncthreads();

    const int lrow = ((lane >> 3) & 1) * 8 + (lane & 7);
    const uint32_t chi = (uint32_t)((lane >> 4) << 4);
    const uint32_t sw = (uint32_t)((lane & 7) << 4);
    const uint4* gb = reinterpret_cast<const uint4*>(g_BF);

    // ---- two M-halves: 16 live accumulators each ----
#pragma unroll
    for (int mt = 0; mt < 2; mt++) {
        float acc[4][4];
#pragma unroll
        for (int b = 0; b < 4; b++)
#pragma unroll
            for (int cc = 0; cc < 4; cc++) acc[b][cc] = 0.f;

#pragma unroll
        for (int kt = 0; kt < 8; kt++) {
            uint32_t a0, a1, a2, a3;
            {
                int r = mgroup * 32 + mt * 16 + lrow;
                uint32_t addr = sbase + (uint32_t)r * 256
                              + (((uint32_t)kt * 32 + chi) ^ sw);
                LDMATRIX_X4(a0, a1, a2, a3, addr);
            }
#pragma unroll
            for (int j = 0; j < 2; j++) {           // nt pair j -> nt = 2j, 2j+1
                uint4 q = __ldg(&gb[(size_t)((kt * 8 + ngroup * 2 + j) * 32 + lane)]);
                MMA16816(acc[2 * j][0], acc[2 * j][1], acc[2 * j][2], acc[2 * j][3],
                         a0, a1, a2, a3, q.x, q.y);
                MMA16816(acc[2 * j + 1][0], acc[2 * j + 1][1],
                         acc[2 * j + 1][2], acc[2 * j + 1][3],
                         a0, a1, a2, a3, q.z, q.w);
            }
        }

        // stage this half's 32 rows (mgroup*32 + mt*16 + 0..15, both mgroups)
        // slot = mgroup*16 + row-within-block; no sync needed before writing
        // (staging was drained by the barrier after the previous half's STG).
#pragma unroll
        for (int half8 = 0; half8 < 2; half8++) {
            int q8 = (lane >> 2) + half8 * 8;       // 0..15 within 16-row block
            int slot = mgroup * 16 + q8;
#pragma unroll
            for (int nt = 0; nt < 4; nt++) {
                uint32_t cbyte = (uint32_t)(ngroup * 32 + nt * 8 + ((lane & 3) << 1)) * 4;
                *reinterpret_cast<float2*>(
                    smem + SMEM_STG + slot * 512 + (cbyte ^ ((uint32_t)(slot & 7) << 5)))
                    = make_float2(acc[nt][half8 * 2], acc[nt][half8 * 2 + 1]);
            }
        }
        __syncthreads();

        // coalesced STG of 32 staged rows
        {
#pragma unroll
            for (int it = 0; it < 4; it++) {
                int idx = tid + it * 256;
                int slot = idx >> 5;
                int u = idx & 31;
                uint32_t logical = (uint32_t)u * 16;
                uint32_t swz = logical ^ ((uint32_t)(slot & 7) << 5);
                uint4 val = *reinterpret_cast<const uint4*>(
                    smem + SMEM_STG + slot * 512 + swz);
                size_t grow = rowBase + (size_t)((slot >> 4) * 32 + mt * 16 + (slot & 15));
                __stcs(reinterpret_cast<uint4*>(
                           reinterpret_cast<char*>(out + grow * ODIM) + logical),
                       val);
            }
        }
        __syncthreads();   // staging drained before next half overwrites
    }
}

// ---------------------------------------------------------------------------
extern "C" void kernel_launch(void* const* d_in, const int* in_sizes, int n_in,
                              void* d_out, int out_size) {
    const float* x = (const float*)d_in[0];
    const float* coef = (const float*)d_in[1];
    const float* tr = (const float*)d_in[2];
    float* out = (float*)d_out;

    cudaFuncSetAttribute(fused_tanh_gemm_kernel,
                         cudaFuncAttributeMaxDynamicSharedMemorySize, SMEM_TOTAL);

    // spread prep over 64 SMs to halve its latency (overlapped via PDL)
    prep_w_kernel<<<64, 128>>>(coef);

    int rows = in_sizes[0] / IDIM;     // 131072
    int grid = rows / TILE_M;          // 2048

    cudaLaunchConfig_t cfg = {};
    cfg.gridDim = dim3((unsigned)grid);
    cfg.blockDim = dim3(256);
    cfg.dynamicSmemBytes = SMEM_TOTAL;
    cfg.stream = 0;
    cudaLaunchAttribute attrs[1];
    attrs[0].id = cudaLaunchAttributeProgrammaticStreamSerialization;
    attrs[0].val.programmaticStreamSerializationAllowed = 1;
    cfg.attrs = attrs;
    cfg.numAttrs = 1;
    cudaLaunchKernelEx(&cfg, fused_tanh_gemm_kernel, x, tr, out);
}

// round 12
// speedup vs baseline: 1.9375x; 1.9375x over previous
#include <cuda_runtime.h>
#include <cuda_fp16.h>
#include <cstdint>

// out[b,o] = sum_i tanh(x[b,i]*t) * W[o,i],  W = sum_p coef[o,i,p]
// B=131072, I=O=128. fp32 in/out.
//
// mma.sync.m16n8k16 fp16 (fp32 accum), fp16 W (rel_err ~2.7e-4).
// R9 base (regs 64, 4 CTAs/SM) + TMA bulk-store epilogue (linear staging,
// rotation-conflict-free STS) + MLP=8 x loads. PDL overlap of prep_w.

static constexpr int IDIM = 128;
static constexpr int ODIM = 128;
static constexpr int TILE_M = 64;

// B fragments, paired layout: block (kt, nt2) of 32 lanes x uint4 =
// [ntg=2*nt2 reg0, reg1, ntg=2*nt2+1 reg0, reg1]. 32KB, L1/L2-hot.
__device__ uint32_t g_BF[8 * 8 * 32 * 4];

// ---------------------------------------------------------------------------
__global__ void prep_w_kernel(const float* __restrict__ coef) {
    int idx = blockIdx.x * blockDim.x + threadIdx.x;   // 0..8191
    int nt = idx >> 9;
    int kt = (idx >> 6) & 7;
    int lane = (idx >> 1) & 31;
    int reg = idx & 1;
    int n = nt * 8 + (lane >> 2);
    int k = kt * 16 + (lane & 3) * 2 + reg * 8;

    const float4* c0 = reinterpret_cast<const float4*>(coef + ((size_t)n * 128 + k) * 16);
    const float4* c1 = reinterpret_cast<const float4*>(coef + ((size_t)n * 128 + k + 1) * 16);
    float4 v[8];
#pragma unroll
    for (int j = 0; j < 4; j++) v[j] = c0[j];
#pragma unroll
    for (int j = 0; j < 4; j++) v[4 + j] = c1[j];
    float s0 = 0.f, s1 = 0.f;
#pragma unroll
    for (int j = 0; j < 4; j++) s0 += (v[j].x + v[j].y) + (v[j].z + v[j].w);
#pragma unroll
    for (int j = 0; j < 4; j++) s1 += (v[4 + j].x + v[4 + j].y) + (v[4 + j].z + v[4 + j].w);
    __half2 hh = __floats2half2_rn(s0, s1);
    int pos = ((kt * 8 + (nt >> 1)) * 32 + lane) * 4 + (nt & 1) * 2 + reg;
    g_BF[pos] = *reinterpret_cast<uint32_t*>(&hh);
}

// ---------------------------------------------------------------------------
// 5-op tanh: tanh(v*t) = 1 - 2/(e^{2vt}+1), e via ex2.approx. Clamp-free.
// ---------------------------------------------------------------------------
__device__ __forceinline__ float tanh_fast(float v, float c) {
    float e, r;
    asm("ex2.approx.f32 %0, %1;" : "=f"(e) : "f"(v * c));
    asm("rcp.approx.f32 %0, %1;" : "=f"(r) : "f"(e + 1.f));
    return fmaf(-2.f, r, 1.f);
}

__device__ __forceinline__ uint32_t pack_h2(float a, float b) {
    __half2 h = __floats2half2_rn(a, b);
    return *reinterpret_cast<uint32_t*>(&h);
}

#define MMA16816(d0, d1, d2, d3, a0, a1, a2, a3, b0, b1)                      \
    asm volatile(                                                             \
        "mma.sync.aligned.m16n8k16.row.col.f32.f16.f16.f32 "                  \
        "{%0,%1,%2,%3}, {%4,%5,%6,%7}, {%8,%9}, {%0,%1,%2,%3};"               \
        : "+f"(d0), "+f"(d1), "+f"(d2), "+f"(d3)                              \
        : "r"(a0), "r"(a1), "r"(a2), "r"(a3), "r"(b0), "r"(b1))

#define LDMATRIX_X4(a0, a1, a2, a3, addr)                                     \
    asm volatile(                                                             \
        "ldmatrix.sync.aligned.m8n8.x4.shared.b16 {%0,%1,%2,%3}, [%4];"       \
        : "=r"(a0), "=r"(a1), "=r"(a2), "=r"(a3) : "r"(addr))

// SMEM: [0,16K) A tile (64 rows x 256B, XOR-16B swizzle);
//       [16K,48K) LINEAR fp32 staging (64 rows x 512B) for TMA bulk store.
static constexpr int SMEM_STG = 16384;
static constexpr int SMEM_TOTAL = 16384 + 32768;   // 48 KB

// ---------------------------------------------------------------------------
__global__ __launch_bounds__(256, 4) void fused_tanh_gemm_kernel(
    const float* __restrict__ x, const float* __restrict__ tanh_range,
    float* __restrict__ out)
{
    extern __shared__ __align__(16) char smem[];
    uint32_t sbase;
    asm("{ .reg .u64 t; cvta.to.shared.u64 t, %1; cvt.u32.u64 %0, t; }"
        : "=r"(sbase) : "l"(smem));

    const int tid = threadIdx.x;
    const int lane = tid & 31;
    const int wid = tid >> 5;
    const int mgroup = wid >> 2;
    const int ngroup = wid & 3;
    const size_t rowBase = (size_t)blockIdx.x * TILE_M;

    // ---- stage 1: MLP=8 front-batched loads + 5-op tanh + swizzled STS ----
    // (independent of prep_w output; overlaps with prep_w under PDL)
    {
        const float c = __ldg(tanh_range) * 2.885390082f;   // 2*log2(e)*t
        const float4* x4 = reinterpret_cast<const float4*>(x + rowBase * IDIM);
        float4 v[8];
#pragma unroll
        for (int p = 0; p < 8; p++)
            v[p] = __ldcs(&x4[(wid * 8 + p) * 32 + lane]);
#pragma unroll
        for (int p = 0; p < 8; p++) {
            int row = wid * 8 + p;
            uint2 hp;
            hp.x = pack_h2(tanh_fast(v[p].x, c), tanh_fast(v[p].y, c));
            hp.y = pack_h2(tanh_fast(v[p].z, c), tanh_fast(v[p].w, c));
            uint32_t byte = (uint32_t)row * 256 + ((lane * 8) ^ ((row & 7) << 4));
            *reinterpret_cast<uint2*>(smem + byte) = hp;
        }
    }

    // prep_w must be complete before any g_BF read
    cudaGridDependencySynchronize();
    __syncthreads();

    // ---- stage 2: MMA ----
    float acc[2][4][4];
#pragma unroll
    for (int a = 0; a < 2; a++)
#pragma unroll
        for (int b = 0; b < 4; b++)
#pragma unroll
            for (int cc = 0; cc < 4; cc++) acc[a][b][cc] = 0.f;

    const int lrow = ((lane >> 3) & 1) * 8 + (lane & 7);
    const uint32_t chi = (uint32_t)((lane >> 4) << 4);
    const uint32_t sw = (uint32_t)((lane & 7) << 4);
    const uint4* gb = reinterpret_cast<const uint4*>(g_BF);

#pragma unroll
    for (int kt = 0; kt < 8; kt++) {
        uint32_t a0[2], a1[2], a2[2], a3[2];
#pragma unroll
        for (int mt = 0; mt < 2; mt++) {
            int mtg = mgroup * 2 + mt;
            int r = mtg * 16 + lrow;
            uint32_t addr = sbase + (uint32_t)r * 256 + (((uint32_t)kt * 32 + chi) ^ sw);
            LDMATRIX_X4(a0[mt], a1[mt], a2[mt], a3[mt], addr);
        }
#pragma unroll
        for (int j = 0; j < 2; j++) {               // nt pair j -> nt = 2j, 2j+1
            uint4 q = __ldg(&gb[(size_t)((kt * 8 + ngroup * 2 + j) * 32 + lane)]);
#pragma unroll
            for (int mt = 0; mt < 2; mt++) {
                MMA16816(acc[mt][2 * j][0], acc[mt][2 * j][1],
                         acc[mt][2 * j][2], acc[mt][2 * j][3],
                         a0[mt], a1[mt], a2[mt], a3[mt], q.x, q.y);
                MMA16816(acc[mt][2 * j + 1][0], acc[mt][2 * j + 1][1],
                         acc[mt][2 * j + 1][2], acc[mt][2 * j + 1][3],
                         a0[mt], a1[mt], a2[mt], a3[mt], q.z, q.w);
            }
        }
    }

    // ---- epilogue: rotation-conflict-free STS into LINEAR staging ----
    // Staged value (r,c) lives at its natural address r*512 + c*4; the
    // rotation nt=(i+q)&3 only reorders which lane writes per pass so each
    // STS.64 hits 32 distinct bank-words (floor 2 phases, no conflicts).
    {
        const int q = lane >> 2, p = lane & 3;
#pragma unroll
        for (int mt = 0; mt < 2; mt++) {
            int r_lo = mgroup * 32 + mt * 16 + q;
#pragma unroll
            for (int i = 0; i < 4; i++) {
                int nt = (i + q) & 3;
                uint32_t cbyte = (uint32_t)(ngroup * 128 + nt * 32 + p * 8);
                *reinterpret_cast<float2*>(smem + SMEM_STG + r_lo * 512 + cbyte)
                    = make_float2(acc[mt][nt][0], acc[mt][nt][1]);
                *reinterpret_cast<float2*>(smem + SMEM_STG + (r_lo + 8) * 512 + cbyte)
                    = make_float2(acc[mt][nt][2], acc[mt][nt][3]);
            }
        }
    }
    __syncthreads();

    // ---- one 32KB TMA bulk store: staging -> out[rowBase*128 ...] ----
    if (tid == 0) {
        asm volatile("fence.proxy.async;" ::: "memory");
        asm volatile(
            "cp.async.bulk.global.shared::cta.bulk_group [%0], [%1], %2;"
            :: "l"(out + rowBase * ODIM), "r"(sbase + SMEM_STG), "r"(32768)
            : "memory");
        asm volatile("cp.async.bulk.commit_group;" ::: "memory");
        asm volatile("cp.async.bulk.wait_group.read 0;" ::: "memory");
    }
    __syncthreads();   // keep smem alive until the bulk read completes
}

// ---------------------------------------------------------------------------
extern "C" void kernel_launch(void* const* d_in, const int* in_sizes, int n_in,
                              void* d_out, int out_size) {
    const float* x = (const float*)d_in[0];
    const float* coef = (const float*)d_in[1];
    const float* tr = (const float*)d_in[2];
    float* out = (float*)d_out;

    cudaFuncSetAttribute(fused_tanh_gemm_kernel,
                         cudaFuncAttributeMaxDynamicSharedMemorySize, SMEM_TOTAL);

    // spread prep over 64 SMs (overlapped via PDL)
    prep_w_kernel<<<64, 128>>>(coef);

    int rows = in_sizes[0] / IDIM;     // 131072
    int grid = rows / TILE_M;          // 2048

    cudaLaunchConfig_t cfg = {};
    cfg.gridDim = dim3((unsigned)grid);
    cfg.blockDim = dim3(256);
    cfg.dynamicSmemBytes = SMEM_TOTAL;
    cfg.stream = 0;
    cudaLaunchAttribute attrs[1];
    attrs[0].id = cudaLaunchAttributeProgrammaticStreamSerialization;
    attrs[0].val.programmaticStreamSerializationAllowed = 1;
    cfg.attrs = attrs;
    cfg.numAttrs = 1;
    cudaLaunchKernelEx(&cfg, fused_tanh_gemm_kernel, x, tr, out);
}

// round 13
// speedup vs baseline: 2.1653x; 1.1176x over previous
#include <cuda_runtime.h>
#include <cuda_fp16.h>
#include <cstdint>

// out[b,o] = sum_i tanh(x[b,i]*t) * W[o,i],  W = sum_p coef[o,i,p]
// B=131072, I=O=128. fp32 in/out.
//
// mma.sync.m16n8k16 fp16 (fp32 accum), fp16 W (rel_err ~2.7e-4).
// Persistent CTAs (grid=608), cp.async double-role staging: next tile's x
// streams into SMEM during current tile's MMA. R9 fragment paths otherwise.

static constexpr int IDIM = 128;
static constexpr int ODIM = 128;
static constexpr int TILE_M = 64;

// B fragments, paired layout: block (kt, nt2) of 32 lanes x uint4 =
// [ntg=2*nt2 reg0, reg1, ntg=2*nt2+1 reg0, reg1]. 32KB, L1/L2-hot.
__device__ uint32_t g_BF[8 * 8 * 32 * 4];

// ---------------------------------------------------------------------------
__global__ void prep_w_kernel(const float* __restrict__ coef) {
    int idx = blockIdx.x * blockDim.x + threadIdx.x;   // 0..8191
    int nt = idx >> 9;
    int kt = (idx >> 6) & 7;
    int lane = (idx >> 1) & 31;
    int reg = idx & 1;
    int n = nt * 8 + (lane >> 2);
    int k = kt * 16 + (lane & 3) * 2 + reg * 8;

    const float4* c0 = reinterpret_cast<const float4*>(coef + ((size_t)n * 128 + k) * 16);
    const float4* c1 = reinterpret_cast<const float4*>(coef + ((size_t)n * 128 + k + 1) * 16);
    float4 v[8];
#pragma unroll
    for (int j = 0; j < 4; j++) v[j] = c0[j];
#pragma unroll
    for (int j = 0; j < 4; j++) v[4 + j] = c1[j];
    float s0 = 0.f, s1 = 0.f;
#pragma unroll
    for (int j = 0; j < 4; j++) s0 += (v[j].x + v[j].y) + (v[j].z + v[j].w);
#pragma unroll
    for (int j = 0; j < 4; j++) s1 += (v[4 + j].x + v[4 + j].y) + (v[4 + j].z + v[4 + j].w);
    __half2 hh = __floats2half2_rn(s0, s1);
    int pos = ((kt * 8 + (nt >> 1)) * 32 + lane) * 4 + (nt & 1) * 2 + reg;
    g_BF[pos] = *reinterpret_cast<uint32_t*>(&hh);
}

// ---------------------------------------------------------------------------
// 5-op tanh: tanh(v*t) = 1 - 2/(e^{2vt}+1), e via ex2.approx. Clamp-free.
// ---------------------------------------------------------------------------
__device__ __forceinline__ float tanh_fast(float v, float c) {
    float e, r;
    asm("ex2.approx.f32 %0, %1;" : "=f"(e) : "f"(v * c));
    asm("rcp.approx.f32 %0, %1;" : "=f"(r) : "f"(e + 1.f));
    return fmaf(-2.f, r, 1.f);
}

__device__ __forceinline__ uint32_t pack_h2(float a, float b) {
    __half2 h = __floats2half2_rn(a, b);
    return *reinterpret_cast<uint32_t*>(&h);
}

#define MMA16816(d0, d1, d2, d3, a0, a1, a2, a3, b0, b1)                      \
    asm volatile(                                                             \
        "mma.sync.aligned.m16n8k16.row.col.f32.f16.f16.f32 "                  \
        "{%0,%1,%2,%3}, {%4,%5,%6,%7}, {%8,%9}, {%0,%1,%2,%3};"               \
        : "+f"(d0), "+f"(d1), "+f"(d2), "+f"(d3)                              \
        : "r"(a0), "r"(a1), "r"(a2), "r"(a3), "r"(b0), "r"(b1))

#define LDMATRIX_X4(a0, a1, a2, a3, addr)                                     \
    asm volatile(                                                             \
        "ldmatrix.sync.aligned.m8n8.x4.shared.b16 {%0,%1,%2,%3}, [%4];"       \
        : "=r"(a0), "=r"(a1), "=r"(a2), "=r"(a3) : "r"(addr))

#define CP_ASYNC_16(dst, src)                                                 \
    asm volatile("cp.async.cg.shared.global [%0], [%1], 16;"                  \
                 :: "r"(dst), "l"(src) : "memory")

// SMEM: [0,32K) XS raw x staging (64 rows x 512B, linear);
//       [32K,48K) AF fragment tile (64 rows x 256B, XOR-16B swizzle),
//                 reused as 32-row x 512B restage buffer in the epilogue.
static constexpr int SMEM_AF = 32768;
static constexpr int SMEM_TOTAL = 49152;   // 48 KB -> 4 CTAs/SM

// ---------------------------------------------------------------------------
__global__ __launch_bounds__(256, 4) void fused_tanh_gemm_kernel(
    const float* __restrict__ x, const float* __restrict__ tanh_range,
    float* __restrict__ out, int ntiles)
{
    extern __shared__ __align__(16) char smem[];
    uint32_t sbase;
    asm("{ .reg .u64 t; cvta.to.shared.u64 t, %1; cvt.u32.u64 %0, t; }"
        : "=r"(sbase) : "l"(smem));

    const int tid = threadIdx.x;
    const int lane = tid & 31;
    const int wid = tid >> 5;
    const int mgroup = wid >> 2;
    const int ngroup = wid & 3;

    // ---- prologue: stream first tile's x into XS (overlaps prep_w via PDL) --
    {
        const char* src = reinterpret_cast<const char*>(x)
                        + (size_t)blockIdx.x * TILE_M * IDIM * 4 + tid * 16;
        uint32_t dst = sbase + tid * 16;
#pragma unroll
        for (int p = 0; p < 8; p++)
            CP_ASYNC_16(dst + p * 4096, src + (size_t)p * 4096);
        asm volatile("cp.async.commit_group;" ::: "memory");
    }

    // prep_w must be complete before any g_BF read
    cudaGridDependencySynchronize();

    const float c = __ldg(tanh_range) * 2.885390082f;   // 2*log2(e)*t

    const int lrow = ((lane >> 3) & 1) * 8 + (lane & 7);
    const uint32_t chi = (uint32_t)((lane >> 4) << 4);
    const uint32_t sw = (uint32_t)((lane & 7) << 4);
    const uint4* gb = reinterpret_cast<const uint4*>(g_BF);

    for (int i = blockIdx.x; i < ntiles; i += gridDim.x) {
        // XS filled for tile i (also orders epilogue STG reads of AF)
        asm volatile("cp.async.wait_group 0;" ::: "memory");
        __syncthreads();

        // ---- tanh: XS (LDS.128) -> AF fragments (swizzled STS.64) ----
#pragma unroll
        for (int p = 0; p < 8; p++) {
            int row = wid * 8 + p;
            float4 v = *reinterpret_cast<const float4*>(smem + row * 512 + lane * 16);
            uint2 hp;
            hp.x = pack_h2(tanh_fast(v.x, c), tanh_fast(v.y, c));
            hp.y = pack_h2(tanh_fast(v.z, c), tanh_fast(v.w, c));
            uint32_t byte = (uint32_t)row * 256 + ((lane * 8) ^ ((row & 7) << 4));
            *reinterpret_cast<uint2*>(smem + SMEM_AF + byte) = hp;
        }
        __syncthreads();   // XS reads + AF writes complete

        // ---- prefetch next tile's x into XS (overlaps MMA + epilogue) ----
        int inext = i + gridDim.x;
        if (inext < ntiles) {
            const char* src = reinterpret_cast<const char*>(x)
                            + (size_t)inext * TILE_M * IDIM * 4 + tid * 16;
            uint32_t dst = sbase + tid * 16;
#pragma unroll
            for (int p = 0; p < 8; p++)
                CP_ASYNC_16(dst + p * 4096, src + (size_t)p * 4096);
        }
        asm volatile("cp.async.commit_group;" ::: "memory");

        // ---- MMA ----
        float acc[2][4][4];
#pragma unroll
        for (int a = 0; a < 2; a++)
#pragma unroll
            for (int b = 0; b < 4; b++)
#pragma unroll
                for (int cc = 0; cc < 4; cc++) acc[a][b][cc] = 0.f;

#pragma unroll
        for (int kt = 0; kt < 8; kt++) {
            uint32_t a0[2], a1[2], a2[2], a3[2];
#pragma unroll
            for (int mt = 0; mt < 2; mt++) {
                int r = (mgroup * 2 + mt) * 16 + lrow;
                uint32_t addr = sbase + SMEM_AF + (uint32_t)r * 256
                              + (((uint32_t)kt * 32 + chi) ^ sw);
                LDMATRIX_X4(a0[mt], a1[mt], a2[mt], a3[mt], addr);
            }
#pragma unroll
            for (int j = 0; j < 2; j++) {           // nt pair j -> nt = 2j, 2j+1
                uint4 q = __ldg(&gb[(size_t)((kt * 8 + ngroup * 2 + j) * 32 + lane)]);
#pragma unroll
                for (int mt = 0; mt < 2; mt++) {
                    MMA16816(acc[mt][2 * j][0], acc[mt][2 * j][1],
                             acc[mt][2 * j][2], acc[mt][2 * j][3],
                             a0[mt], a1[mt], a2[mt], a3[mt], q.x, q.y);
                    MMA16816(acc[mt][2 * j + 1][0], acc[mt][2 * j + 1][1],
                             acc[mt][2 * j + 1][2], acc[mt][2 * j + 1][3],
                             a0[mt], a1[mt], a2[mt], a3[mt], q.z, q.w);
                }
            }
        }

        // ---- epilogue: restage via AF (two 32-row halves), coalesced STG ----
        const size_t rowBase = (size_t)i * TILE_M;
        __syncthreads();   // all ldmatrix reads of AF done
#pragma unroll
        for (int h = 0; h < 2; h++) {
            if (mgroup == h) {
#pragma unroll
                for (int mt = 0; mt < 2; mt++) {
                    int lr = mt * 16 + (lane >> 2);   // 0..31 local row
                    int lr2 = lr + 8;
#pragma unroll
                    for (int nt = 0; nt < 4; nt++) {
                        uint32_t cbyte =
                            (uint32_t)(ngroup * 32 + nt * 8 + ((lane & 3) << 1)) * 4;
                        *reinterpret_cast<float2*>(
                            smem + SMEM_AF + lr * 512 + (cbyte ^ ((uint32_t)(lr & 7) << 5)))
                            = make_float2(acc[mt][nt][0], acc[mt][nt][1]);
                        *reinterpret_cast<float2*>(
                            smem + SMEM_AF + lr2 * 512 + (cbyte ^ ((uint32_t)(lr2 & 7) << 5)))
                            = make_float2(acc[mt][nt][2], acc[mt][nt][3]);
                    }
                }
            }
            __syncthreads();
            float* obase = out + (rowBase + (size_t)h * 32) * ODIM;
#pragma unroll
            for (int it = 0; it < 4; it++) {
                int idx = tid + it * 256;
                int row = idx >> 5;
                int u = idx & 31;
                uint32_t logical = (uint32_t)u * 16;
                uint32_t swz = logical ^ ((uint32_t)(row & 7) << 5);
                uint4 val = *reinterpret_cast<const uint4*>(
                    smem + SMEM_AF + row * 512 + swz);
                __stcs(reinterpret_cast<uint4*>(
                           reinterpret_cast<char*>(obase + (size_t)row * ODIM) + logical),
                       val);
            }
            if (h == 0) __syncthreads();   // half-0 reads done before half-1 staging
        }
        // loop-head wait+syncthreads orders half-1 STG reads vs next tanh writes
    }
}

// ---------------------------------------------------------------------------
extern "C" void kernel_launch(void* const* d_in, const int* in_sizes, int n_in,
                              void* d_out, int out_size) {
    const float* x = (const float*)d_in[0];
    const float* coef = (const float*)d_in[1];
    const float* tr = (const float*)d_in[2];
    float* out = (float*)d_out;

    cudaFuncSetAttribute(fused_tanh_gemm_kernel,
                         cudaFuncAttributeMaxDynamicSharedMemorySize, SMEM_TOTAL);

    // spread prep over 64 SMs (overlapped via PDL)
    prep_w_kernel<<<64, 128>>>(coef);

    int rows = in_sizes[0] / IDIM;     // 131072
    int ntiles = rows / TILE_M;        // 2048
    int grid = 608;                    // 152 SMs x 4 CTAs
    if (grid > ntiles) grid = ntiles;

    cudaLaunchConfig_t cfg = {};
    cfg.gridDim = dim3((unsigned)grid);
    cfg.blockDim = dim3(256);
    cfg.dynamicSmemBytes = SMEM_TOTAL;
    cfg.stream = 0;
    cudaLaunchAttribute attrs[1];
    attrs[0].id = cudaLaunchAttributeProgrammaticStreamSerialization;
    attrs[0].val.programmaticStreamSerializationAllowed = 1;
    cfg.attrs = attrs;
    cfg.numAttrs = 1;
    cudaLaunchKernelEx(&cfg, fused_tanh_gemm_kernel, x, tr, out, ntiles);
}

// round 14
// speedup vs baseline: 2.6044x; 1.2028x over previous
#include <cuda_runtime.h>
#include <cuda_fp16.h>
#include <cstdint>

// out[b,o] = sum_i tanh(x[b,i]*t) * W[o,i],  W = sum_p coef[o,i,p]
// B=131072, I=O=128. fp32 in/out.
//
// mma.sync.m16n8k16 fp16 (fp32 accum), fp16 W (rel_err ~2.7e-4).
// R9 warp-level code re-tiled: 128-thread CTAs (TILE_M=32, grid=4096),
// 8 CTAs/SM for phase decorrelation. 8KB smem/CTA (A tile = staging).

static constexpr int IDIM = 128;
static constexpr int ODIM = 128;
static constexpr int TILE_M = 32;

// B fragments, paired layout: block (kt, nt2) of 32 lanes x uint4 =
// [ntg=2*nt2 reg0, reg1, ntg=2*nt2+1 reg0, reg1]. 32KB, L1/L2-hot.
__device__ uint32_t g_BF[8 * 8 * 32 * 4];

// ---------------------------------------------------------------------------
__global__ void prep_w_kernel(const float* __restrict__ coef) {
    int idx = blockIdx.x * blockDim.x + threadIdx.x;   // 0..8191
    int nt = idx >> 9;
    int kt = (idx >> 6) & 7;
    int lane = (idx >> 1) & 31;
    int reg = idx & 1;
    int n = nt * 8 + (lane >> 2);
    int k = kt * 16 + (lane & 3) * 2 + reg * 8;

    const float4* c0 = reinterpret_cast<const float4*>(coef + ((size_t)n * 128 + k) * 16);
    const float4* c1 = reinterpret_cast<const float4*>(coef + ((size_t)n * 128 + k + 1) * 16);
    float4 v[8];
#pragma unroll
    for (int j = 0; j < 4; j++) v[j] = c0[j];
#pragma unroll
    for (int j = 0; j < 4; j++) v[4 + j] = c1[j];
    float s0 = 0.f, s1 = 0.f;
#pragma unroll
    for (int j = 0; j < 4; j++) s0 += (v[j].x + v[j].y) + (v[j].z + v[j].w);
#pragma unroll
    for (int j = 0; j < 4; j++) s1 += (v[4 + j].x + v[4 + j].y) + (v[4 + j].z + v[4 + j].w);
    __half2 hh = __floats2half2_rn(s0, s1);
    int pos = ((kt * 8 + (nt >> 1)) * 32 + lane) * 4 + (nt & 1) * 2 + reg;
    g_BF[pos] = *reinterpret_cast<uint32_t*>(&hh);
}

// ---------------------------------------------------------------------------
// 5-op tanh: tanh(v*t) = 1 - 2/(e^{2vt}+1), e via ex2.approx. Clamp-free.
// ---------------------------------------------------------------------------
__device__ __forceinline__ float tanh_fast(float v, float c) {
    float e, r;
    asm("ex2.approx.f32 %0, %1;" : "=f"(e) : "f"(v * c));
    asm("rcp.approx.f32 %0, %1;" : "=f"(r) : "f"(e + 1.f));
    return fmaf(-2.f, r, 1.f);
}

__device__ __forceinline__ uint32_t pack_h2(float a, float b) {
    __half2 h = __floats2half2_rn(a, b);
    return *reinterpret_cast<uint32_t*>(&h);
}

#define MMA16816(d0, d1, d2, d3, a0, a1, a2, a3, b0, b1)                      \
    asm volatile(                                                             \
        "mma.sync.aligned.m16n8k16.row.col.f32.f16.f16.f32 "                  \
        "{%0,%1,%2,%3}, {%4,%5,%6,%7}, {%8,%9}, {%0,%1,%2,%3};"               \
        : "+f"(d0), "+f"(d1), "+f"(d2), "+f"(d3)                              \
        : "r"(a0), "r"(a1), "r"(a2), "r"(a3), "r"(b0), "r"(b1))

#define LDMATRIX_X4(a0, a1, a2, a3, addr)                                     \
    asm volatile(                                                             \
        "ldmatrix.sync.aligned.m8n8.x4.shared.b16 {%0,%1,%2,%3}, [%4];"       \
        : "=r"(a0), "=r"(a1), "=r"(a2), "=r"(a3) : "r"(addr))

// SMEM: 8KB. Phase 1: A tile 32 rows x 256B (XOR-16B swizzle).
// Epilogue: reused as 16 rows x 512B fp32 staging (XOR-32B swizzle), 2 halves.
static constexpr int SMEM_TOTAL = 8192;

// ---------------------------------------------------------------------------
__global__ __launch_bounds__(128, 8) void fused_tanh_gemm_kernel(
    const float* __restrict__ x, const float* __restrict__ tanh_range,
    float* __restrict__ out)
{
    extern __shared__ __align__(16) char smem[];
    uint32_t sbase;
    asm("{ .reg .u64 t; cvta.to.shared.u64 t, %1; cvt.u32.u64 %0, t; }"
        : "=r"(sbase) : "l"(smem));

    const int tid = threadIdx.x;
    const int lane = tid & 31;
    const int wid = tid >> 5;          // 0..3 = ngroup
    const size_t rowBase = (size_t)blockIdx.x * TILE_M;

    // ---- stage 1: front-batched coalesced loads + tanh + swizzled STS ----
    // warp w handles rows w*8..w*8+7 (overlaps prep_w under PDL)
    {
        const float c = __ldg(tanh_range) * 2.885390082f;   // 2*log2(e)*t
        const float4* x4 = reinterpret_cast<const float4*>(x + rowBase * IDIM);
        float4 v[8];
#pragma unroll
        for (int p = 0; p < 8; p++)
            v[p] = __ldcs(&x4[(wid * 8 + p) * 32 + lane]);
#pragma unroll
        for (int p = 0; p < 8; p++) {
            int row = wid * 8 + p;
            uint2 hp;
            hp.x = pack_h2(tanh_fast(v[p].x, c), tanh_fast(v[p].y, c));
            hp.y = pack_h2(tanh_fast(v[p].z, c), tanh_fast(v[p].w, c));
            uint32_t byte = (uint32_t)row * 256 + ((lane * 8) ^ ((row & 7) << 4));
            *reinterpret_cast<uint2*>(smem + byte) = hp;
        }
    }

    // prep_w must be complete before any g_BF read
    cudaGridDependencySynchronize();
    __syncthreads();

    // ---- stage 2: MMA (identical per-warp structure to R9) ----
    float acc[2][4][4];
#pragma unroll
    for (int a = 0; a < 2; a++)
#pragma unroll
        for (int b = 0; b < 4; b++)
#pragma unroll
            for (int cc = 0; cc < 4; cc++) acc[a][b][cc] = 0.f;

    const int lrow = ((lane >> 3) & 1) * 8 + (lane & 7);
    const uint32_t chi = (uint32_t)((lane >> 4) << 4);
    const uint32_t sw = (uint32_t)((lane & 7) << 4);
    const uint4* gb = reinterpret_cast<const uint4*>(g_BF);

#pragma unroll
    for (int kt = 0; kt < 8; kt++) {
        uint32_t a0[2], a1[2], a2[2], a3[2];
#pragma unroll
        for (int mt = 0; mt < 2; mt++) {
            int r = mt * 16 + lrow;
            uint32_t addr = sbase + (uint32_t)r * 256 + (((uint32_t)kt * 32 + chi) ^ sw);
            LDMATRIX_X4(a0[mt], a1[mt], a2[mt], a3[mt], addr);
        }
#pragma unroll
        for (int j = 0; j < 2; j++) {               // nt pair j -> nt = 2j, 2j+1
            uint4 q = __ldg(&gb[(size_t)((kt * 8 + wid * 2 + j) * 32 + lane)]);
#pragma unroll
            for (int mt = 0; mt < 2; mt++) {
                MMA16816(acc[mt][2 * j][0], acc[mt][2 * j][1],
                         acc[mt][2 * j][2], acc[mt][2 * j][3],
                         a0[mt], a1[mt], a2[mt], a3[mt], q.x, q.y);
                MMA16816(acc[mt][2 * j + 1][0], acc[mt][2 * j + 1][1],
                         acc[mt][2 * j + 1][2], acc[mt][2 * j + 1][3],
                         a0[mt], a1[mt], a2[mt], a3[mt], q.z, q.w);
            }
        }
    }

    // ---- epilogue: two 16-row halves restaged through the 8KB A region ----
    __syncthreads();   // all ldmatrix A-tile reads complete
#pragma unroll
    for (int h = 0; h < 2; h++) {
        // stage rows h*16 .. h*16+15 (all warps hold acc[h] for these rows)
#pragma unroll
        for (int half8 = 0; half8 < 2; half8++) {
            int slot = (lane >> 2) + half8 * 8;    // 0..15
#pragma unroll
            for (int nt = 0; nt < 4; nt++) {
                uint32_t cbyte = (uint32_t)(wid * 32 + nt * 8 + ((lane & 3) << 1)) * 4;
                *reinterpret_cast<float2*>(
                    smem + slot * 512 + (cbyte ^ ((uint32_t)(slot & 7) << 5)))
                    = make_float2(acc[h][nt][half8 * 2], acc[h][nt][half8 * 2 + 1]);
            }
        }
        __syncthreads();

        // coalesced STG of 16 staged rows (16 x 512B = 8KB)
        float* obase = out + (rowBase + (size_t)h * 16) * ODIM;
#pragma unroll
        for (int it = 0; it < 4; it++) {
            int idx = tid + it * 128;
            int slot = idx >> 5;                   // 0..15
            int u = idx & 31;
            uint32_t logical = (uint32_t)u * 16;
            uint32_t swz = logical ^ ((uint32_t)(slot & 7) << 5);
            uint4 val = *reinterpret_cast<const uint4*>(smem + slot * 512 + swz);
            __stcs(reinterpret_cast<uint4*>(
                       reinterpret_cast<char*>(obase + (size_t)slot * ODIM) + logical),
                   val);
        }
        if (h == 0) __syncthreads();   // half-0 reads done before half-1 staging
    }
}

// ---------------------------------------------------------------------------
extern "C" void kernel_launch(void* const* d_in, const int* in_sizes, int n_in,
                              void* d_out, int out_size) {
    const float* x = (const float*)d_in[0];
    const float* coef = (const float*)d_in[1];
    const float* tr = (const float*)d_in[2];
    float* out = (float*)d_out;

    cudaFuncSetAttribute(fused_tanh_gemm_kernel,
                         cudaFuncAttributeMaxDynamicSharedMemorySize, SMEM_TOTAL);

    // R8-best prep config (overlapped via PDL)
    prep_w_kernel<<<32, 256>>>(coef);

    int rows = in_sizes[0] / IDIM;     // 131072
    int grid = rows / TILE_M;          // 4096

    cudaLaunchConfig_t cfg = {};
    cfg.gridDim = dim3((unsigned)grid);
    cfg.blockDim = dim3(128);
    cfg.dynamicSmemBytes = SMEM_TOTAL;
    cfg.stream = 0;
    cudaLaunchAttribute attrs[1];
    attrs[0].id = cudaLaunchAttributeProgrammaticStreamSerialization;
    attrs[0].val.programmaticStreamSerializationAllowed = 1;
    cfg.attrs = attrs;
    cfg.numAttrs = 1;
    cudaLaunchKernelEx(&cfg, fused_tanh_gemm_kernel, x, tr, out);
}

// round 15
// speedup vs baseline: 2.6950x; 1.0348x over previous
#include <cuda_runtime.h>
#include <cuda_fp16.h>
#include <cstdint>

// out[b,o] = sum_i tanh(x[b,i]*t) * W[o,i],  W = sum_p coef[o,i,p]
// B=131072, I=O=128. fp32 in/out.
//
// mma.sync.m16n8k16 fp16 (fp32 accum), fp16 W (rel_err ~2.7e-4).
// R14 GEMM (TILE_M=32, 128-thr CTAs, 8/SM) + early-trigger PDL prep.

static constexpr int IDIM = 128;
static constexpr int ODIM = 128;
static constexpr int TILE_M = 32;

// B fragments, paired layout: block (kt, nt2) of 32 lanes x uint4 =
// [ntg=2*nt2 reg0, reg1, ntg=2*nt2+1 reg0, reg1]. 32KB, L1/L2-hot.
__device__ uint32_t g_BF[8 * 8 * 32 * 4];

// ---------------------------------------------------------------------------
__global__ void prep_w_kernel(const float* __restrict__ coef) {
    int idx = blockIdx.x * blockDim.x + threadIdx.x;   // 0..8191
    int nt = idx >> 9;
    int kt = (idx >> 6) & 7;
    int lane = (idx >> 1) & 31;
    int reg = idx & 1;
    int n = nt * 8 + (lane >> 2);
    int k = kt * 16 + (lane & 3) * 2 + reg * 8;

    const float4* c0 = reinterpret_cast<const float4*>(coef + ((size_t)n * 128 + k) * 16);
    const float4* c1 = reinterpret_cast<const float4*>(coef + ((size_t)n * 128 + k + 1) * 16);
    float4 v[8];
#pragma unroll
    for (int j = 0; j < 4; j++) v[j] = c0[j];
#pragma unroll
    for (int j = 0; j < 4; j++) v[4 + j] = c1[j];
    float s0 = 0.f, s1 = 0.f;
#pragma unroll
    for (int j = 0; j < 4; j++) s0 += (v[j].x + v[j].y) + (v[j].z + v[j].w);
#pragma unroll
    for (int j = 0; j < 4; j++) s1 += (v[4 + j].x + v[4 + j].y) + (v[4 + j].z + v[4 + j].w);
    __half2 hh = __floats2half2_rn(s0, s1);
    int pos = ((kt * 8 + (nt >> 1)) * 32 + lane) * 4 + (nt & 1) * 2 + reg;
    g_BF[pos] = *reinterpret_cast<uint32_t*>(&hh);

    // Release the dependent GEMM as soon as g_BF is globally visible,
    // overlapping this kernel's retire tail with the GEMM mainloop.
    __threadfence();
    cudaTriggerProgrammaticLaunchCompletion();
}

// ---------------------------------------------------------------------------
// 5-op tanh: tanh(v*t) = 1 - 2/(e^{2vt}+1), e via ex2.approx. Clamp-free.
// ---------------------------------------------------------------------------
__device__ __forceinline__ float tanh_fast(float v, float c) {
    float e, r;
    asm("ex2.approx.f32 %0, %1;" : "=f"(e) : "f"(v * c));
    asm("rcp.approx.f32 %0, %1;" : "=f"(r) : "f"(e + 1.f));
    return fmaf(-2.f, r, 1.f);
}

__device__ __forceinline__ uint32_t pack_h2(float a, float b) {
    __half2 h = __floats2half2_rn(a, b);
    return *reinterpret_cast<uint32_t*>(&h);
}

#define MMA16816(d0, d1, d2, d3, a0, a1, a2, a3, b0, b1)                      \
    asm volatile(                                                             \
        "mma.sync.aligned.m16n8k16.row.col.f32.f16.f16.f32 "                  \
        "{%0,%1,%2,%3}, {%4,%5,%6,%7}, {%8,%9}, {%0,%1,%2,%3};"               \
        : "+f"(d0), "+f"(d1), "+f"(d2), "+f"(d3)                              \
        : "r"(a0), "r"(a1), "r"(a2), "r"(a3), "r"(b0), "r"(b1))

#define LDMATRIX_X4(a0, a1, a2, a3, addr)                                     \
    asm volatile(                                                             \
        "ldmatrix.sync.aligned.m8n8.x4.shared.b16 {%0,%1,%2,%3}, [%4];"       \
        : "=r"(a0), "=r"(a1), "=r"(a2), "=r"(a3) : "r"(addr))

// SMEM: 8KB. Phase 1: A tile 32 rows x 256B (XOR-16B swizzle).
// Epilogue: reused as 16 rows x 512B fp32 staging (XOR-32B swizzle), 2 halves.
static constexpr int SMEM_TOTAL = 8192;

// ---------------------------------------------------------------------------
__global__ __launch_bounds__(128, 8) void fused_tanh_gemm_kernel(
    const float* __restrict__ x, const float* __restrict__ tanh_range,
    float* __restrict__ out)
{
    extern __shared__ __align__(16) char smem[];
    uint32_t sbase;
    asm("{ .reg .u64 t; cvta.to.shared.u64 t, %1; cvt.u32.u64 %0, t; }"
        : "=r"(sbase) : "l"(smem));

    const int tid = threadIdx.x;
    const int lane = tid & 31;
    const int wid = tid >> 5;          // 0..3 = ngroup
    const size_t rowBase = (size_t)blockIdx.x * TILE_M;

    // ---- stage 1: front-batched coalesced loads + tanh + swizzled STS ----
    // warp w handles rows w*8..w*8+7 (overlaps prep_w under PDL)
    {
        const float c = __ldg(tanh_range) * 2.885390082f;   // 2*log2(e)*t
        const float4* x4 = reinterpret_cast<const float4*>(x + rowBase * IDIM);
        float4 v[8];
#pragma unroll
        for (int p = 0; p < 8; p++)
            v[p] = __ldcs(&x4[(wid * 8 + p) * 32 + lane]);
#pragma unroll
        for (int p = 0; p < 8; p++) {
            int row = wid * 8 + p;
            uint2 hp;
            hp.x = pack_h2(tanh_fast(v[p].x, c), tanh_fast(v[p].y, c));
            hp.y = pack_h2(tanh_fast(v[p].z, c), tanh_fast(v[p].w, c));
            uint32_t byte = (uint32_t)row * 256 + ((lane * 8) ^ ((row & 7) << 4));
            *reinterpret_cast<uint2*>(smem + byte) = hp;
        }
    }

    // prep_w writes must be visible before any g_BF read
    cudaGridDependencySynchronize();
    __syncthreads();

    // ---- stage 2: MMA ----
    float acc[2][4][4];
#pragma unroll
    for (int a = 0; a < 2; a++)
#pragma unroll
        for (int b = 0; b < 4; b++)
#pragma unroll
            for (int cc = 0; cc < 4; cc++) acc[a][b][cc] = 0.f;

    const int lrow = ((lane >> 3) & 1) * 8 + (lane & 7);
    const uint32_t chi = (uint32_t)((lane >> 4) << 4);
    const uint32_t sw = (uint32_t)((lane & 7) << 4);
    const uint4* gb = reinterpret_cast<const uint4*>(g_BF);

#pragma unroll
    for (int kt = 0; kt < 8; kt++) {
        uint32_t a0[2], a1[2], a2[2], a3[2];
#pragma unroll
        for (int mt = 0; mt < 2; mt++) {
            int r = mt * 16 + lrow;
            uint32_t addr = sbase + (uint32_t)r * 256 + (((uint32_t)kt * 32 + chi) ^ sw);
            LDMATRIX_X4(a0[mt], a1[mt], a2[mt], a3[mt], addr);
        }
#pragma unroll
        for (int j = 0; j < 2; j++) {               // nt pair j -> nt = 2j, 2j+1
            uint4 q = __ldg(&gb[(size_t)((kt * 8 + wid * 2 + j) * 32 + lane)]);
#pragma unroll
            for (int mt = 0; mt < 2; mt++) {
                MMA16816(acc[mt][2 * j][0], acc[mt][2 * j][1],
                         acc[mt][2 * j][2], acc[mt][2 * j][3],
                         a0[mt], a1[mt], a2[mt], a3[mt], q.x, q.y);
                MMA16816(acc[mt][2 * j + 1][0], acc[mt][2 * j + 1][1],
                         acc[mt][2 * j + 1][2], acc[mt][2 * j + 1][3],
                         a0[mt], a1[mt], a2[mt], a3[mt], q.z, q.w);
            }
        }
    }

    // ---- epilogue: two 16-row halves restaged through the 8KB A region ----
    __syncthreads();   // all ldmatrix A-tile reads complete
#pragma unroll
    for (int h = 0; h < 2; h++) {
        // stage rows h*16 .. h*16+15 (all warps hold acc[h] for these rows)
#pragma unroll
        for (int half8 = 0; half8 < 2; half8++) {
            int slot = (lane >> 2) + half8 * 8;    // 0..15
#pragma unroll
            for (int nt = 0; nt < 4; nt++) {
                uint32_t cbyte = (uint32_t)(wid * 32 + nt * 8 + ((lane & 3) << 1)) * 4;
                *reinterpret_cast<float2*>(
                    smem + slot * 512 + (cbyte ^ ((uint32_t)(slot & 7) << 5)))
                    = make_float2(acc[h][nt][half8 * 2], acc[h][nt][half8 * 2 + 1]);
            }
        }
        __syncthreads();

        // coalesced STG of 16 staged rows (16 x 512B = 8KB)
        float* obase = out + (rowBase + (size_t)h * 16) * ODIM;
#pragma unroll
        for (int it = 0; it < 4; it++) {
            int idx = tid + it * 128;
            int slot = idx >> 5;                   // 0..15
            int u = idx & 31;
            uint32_t logical = (uint32_t)u * 16;
            uint32_t swz = logical ^ ((uint32_t)(slot & 7) << 5);
            uint4 val = *reinterpret_cast<const uint4*>(smem + slot * 512 + swz);
            __stcs(reinterpret_cast<uint4*>(
                       reinterpret_cast<char*>(obase + (size_t)slot * ODIM) + logical),
                   val);
        }
        if (h == 0) __syncthreads();   // half-0 reads done before half-1 staging
    }
}

// ---------------------------------------------------------------------------
extern "C" void kernel_launch(void* const* d_in, const int* in_sizes, int n_in,
                              void* d_out, int out_size) {
    const float* x = (const float*)d_in[0];
    const float* coef = (const float*)d_in[1];
    const float* tr = (const float*)d_in[2];
    float* out = (float*)d_out;

    cudaFuncSetAttribute(fused_tanh_gemm_kernel,
                         cudaFuncAttributeMaxDynamicSharedMemorySize, SMEM_TOTAL);

    // prep spread over 128 SMs; fires PDL trigger right after its writes
    prep_w_kernel<<<128, 64>>>(coef);

    int rows = in_sizes[0] / IDIM;     // 131072
    int grid = rows / TILE_M;          // 4096

    cudaLaunchConfig_t cfg = {};
    cfg.gridDim = dim3((unsigned)grid);
    cfg.blockDim = dim3(128);
    cfg.dynamicSmemBytes = SMEM_TOTAL;
    cfg.stream = 0;
    cudaLaunchAttribute attrs[1];
    attrs[0].id = cudaLaunchAttributeProgrammaticStreamSerialization;
    attrs[0].val.programmaticStreamSerializationAllowed = 1;
    cfg.attrs = attrs;
    cfg.numAttrs = 1;
    cudaLaunchKernelEx(&cfg, fused_tanh_gemm_kernel, x, tr, out);
}